// round 14
// baseline (speedup 1.0000x reference)
#include <cuda_runtime.h>
#include <cuda_fp16.h>
#include <cstdint>
#include <math.h>

// ModulatedConv2D via mma.sync (pure fp16 operands, fp32 accum) implicit GEMM.
// y = sigma[b,o] * conv2d_same(x * style[b,i], GAIN*weight)
// x[16,512,32,32], style[16,512], weight[512,512,3,3] -> out[16,512,32,32]
// R14: software-pipelined ldmatrix fragments (double-buffered) + merged prep.

#define NB 16
#define NC 512
#define HW2 1024
#define EPSV 1e-8f
#define NCHUNK 144   // 16 ic-chunks * 9 taps, K=32 each

static __device__ float g_wsq[NC * NC];
static __device__ float g_sigma[NB * NC];
// weight tiles fp16: [octile(4)][chunk(144)] -> [128 oc][32 k] (8KB)
static __device__ unsigned char g_btiles[(size_t)4 * NCHUNK * 8192];

// ---------------------------------------------------------------------------
__device__ __forceinline__ uint32_t smem_u32(const void* p) {
    uint32_t a;
    asm("{ .reg .u64 t; cvta.to.shared.u64 t, %1; cvt.u32.u64 %0, t; }"
        : "=r"(a) : "l"(p));
    return a;
}
#define CP_ASYNC16(dst, src) \
    asm volatile("cp.async.cg.shared.global [%0], [%1], 16;" :: "r"(dst), "l"(src))
#define CP_COMMIT() asm volatile("cp.async.commit_group;")
#define CP_WAIT0()  asm volatile("cp.async.wait_group 0;" ::: "memory")

#define LDMX4(r, addr) \
    asm volatile("ldmatrix.sync.aligned.m8n8.x4.shared.b16 {%0,%1,%2,%3}, [%4];" \
                 : "=r"((r)[0]), "=r"((r)[1]), "=r"((r)[2]), "=r"((r)[3]) : "r"(addr))
#define LDMX2(r, addr) \
    asm volatile("ldmatrix.sync.aligned.m8n8.x2.shared.b16 {%0,%1}, [%2];" \
                 : "=r"((r)[0]), "=r"((r)[1]) : "r"(addr))

#define MMA16816(d, a, b) \
    asm volatile("mma.sync.aligned.m16n8k16.row.col.f32.f16.f16.f32 " \
                 "{%0,%1,%2,%3}, {%4,%5,%6,%7}, {%8,%9}, {%0,%1,%2,%3};" \
                 : "+f"((d)[0]), "+f"((d)[1]), "+f"((d)[2]), "+f"((d)[3]) \
                 : "r"((a)[0]), "r"((a)[1]), "r"((a)[2]), "r"((a)[3]), \
                   "r"((b)[0]), "r"((b)[1]))

// ---------------------------------------------------------------------------
// prep: ONE pass over weight -> fp16 tiles + wsq (tap-summed per thread).
// grid (16 icch, 4 octile), 256 threads: thread = (oc 0..127) x (khalf 0..1).
// ---------------------------------------------------------------------------
__global__ void prep_all(const float* __restrict__ weight, float gain) {
    const int icch = blockIdx.x, octile = blockIdx.y;
    const int ocl = threadIdx.x >> 1;
    const int kh = (threadIdx.x & 1) * 16;
    const int oc = octile * 128 + ocl;
    float sq[16];
#pragma unroll
    for (int j = 0; j < 16; ++j) sq[j] = 0.f;

#pragma unroll 1
    for (int tap = 0; tap < 9; ++tap) {
        const float* wr = weight + (size_t)oc * 4608 +
                          (size_t)(icch * 32 + kh) * 9 + tap;
        union { __half2 h2[8]; uint4 u4[2]; } H;
#pragma unroll
        for (int j = 0; j < 8; ++j) {
            float v0 = wr[(2 * j) * 9] * gain;
            float v1 = wr[(2 * j + 1) * 9] * gain;
            sq[2 * j]     += v0 * v0;
            sq[2 * j + 1] += v1 * v1;
            H.h2[j] = __halves2half2(__float2half(v0), __float2half(v1));
        }
        unsigned char* blk = g_btiles +
            (size_t)(octile * NCHUNK + icch * 9 + tap) * 8192;
        uint4* dh = (uint4*)(blk + ocl * 64 + kh * 2);
        dh[0] = H.u4[0]; dh[1] = H.u4[1];
    }
#pragma unroll
    for (int j = 0; j < 16; ++j)
        g_wsq[(size_t)oc * NC + icch * 32 + kh + j] = sq[j];
}

__global__ void sigma_kernel(const float* __restrict__ style) {
    const int b = blockIdx.y;
    const int warp = threadIdx.x >> 5, lane = threadIdx.x & 31;
    const int oc = blockIdx.x * 8 + warp;
    float v = 0.f;
    for (int i = lane; i < NC; i += 32) {
        float s = style[b * NC + i];
        v += s * s * g_wsq[oc * NC + i];
    }
#pragma unroll
    for (int off = 16; off; off >>= 1) v += __shfl_xor_sync(0xffffffffu, v, off);
    if (lane == 0) g_sigma[b * NC + oc] = rsqrtf(v + EPSV);
}

// ---------------------------------------------------------------------------
// conv: grid (8 pixtiles, 4 octiles, 16 b), 256 threads (8 warps).
// CTA tile: M=128 oc x N=128 pix. Macro-stage = 3 taps (K=96), 48 stages.
// X per ic-chunk: halo tile 204 rows (6 img rows x 34 cols, padded) x 32 k.
// Fragments double-buffered: LDSM(s+1) issued before MMA(s).
// smem: W stages 2x30720 @0 | X 2x16320 @61440 | sig@94080 | sty@94592
// ---------------------------------------------------------------------------
#define RS 80u          // row stride bytes (40 halves)
#define WIMG 10240u     // one tap's W image
#define WOFF(buf) ((uint32_t)(buf) * 30720u)
#define XOFF(buf) (61440u + (uint32_t)(buf) * 16320u)
#define SM_TOTAL 96768

__global__ void __launch_bounds__(256, 2)
conv_mma(const float* __restrict__ x, const float* __restrict__ style,
         float* __restrict__ out) {
    extern __shared__ char smem[];
    const uint32_t sb = smem_u32(smem);
    const int tid = threadIdx.x;
    const int lane = tid & 31, wid = tid >> 5;
    const int wm = wid & 1;        // m warp (oc): 0..1 -> offset wm*64
    const int wn = wid >> 1;       // n warp (pix row): 0..3
    const int pixtile = blockIdx.x, octile = blockIdx.y, b = blockIdx.z;

    float* s_sig = (float*)(smem + 94080);
    float* s_sty = (float*)(smem + 94592);
    for (int i = tid; i < 128; i += 256) s_sig[i] = g_sigma[b * NC + octile * 128 + i];
    for (int i = tid; i < NC; i += 256) s_sty[i] = style[b * NC + i];
    __syncthreads();

    const float* xb = x + (size_t)b * NC * HW2;
    const unsigned char* wbase = g_btiles + (size_t)octile * NCHUNK * 8192;

    // ---- X-build coords: thread t handles halo-tile pixel row t (0..203) ----
    const bool bact = tid < 204;
    const int blr = tid / 34;                 // local halo row 0..5
    const int bcc = tid % 34 - 1;             // image col -1..32
    const int bimgrow = pixtile * 4 - 1 + blr;
    const bool binimg = bact && ((unsigned)bimgrow < 32u) && ((unsigned)bcc < 32u);
    const float* xpix = xb + (binimg ? (bimgrow * 32 + bcc) : 0);

    // ldmatrix per-lane offsets
    const uint32_t aoff = (uint32_t)(lane & 15) * RS + (uint32_t)(lane >> 4) * 16u;
    uint32_t bb[4];
#pragma unroll
    for (int n = 0; n < 4; ++n)
        bb[n] = (uint32_t)(((wn + 1) * 34 + n * 8 + (lane & 7) + 1)) * RS +
                (uint32_t)((lane >> 3) & 1) * 16u;

    float acc[4][4][4];
#pragma unroll
    for (int m = 0; m < 4; ++m)
#pragma unroll
        for (int n = 0; n < 4; ++n)
#pragma unroll
            for (int r = 0; r < 4; ++r) acc[m][n][r] = 0.f;

    // double-buffered fragments
    uint32_t ah[2][4][4], bh[2][4][2];

    // ---- helpers ----
    auto issueW3 = [&](int mc, uint32_t woff) {
        const unsigned char* src = wbase + (size_t)mc * 3 * 8192;
#pragma unroll
        for (int j = 0; j < 6; ++j) {
            int cidx = tid + j * 256;
            int img = cidx >> 9;
            int rem = cidx & 511;
            int row = rem >> 2, off = rem & 3;
            CP_ASYNC16(sb + woff + img * WIMG + row * RS + off * 16,
                       src + cidx * 16);
        }
        CP_COMMIT();
    };
    auto buildX4_ld = [&](int icch, int kt, float* v) {
#pragma unroll
        for (int j = 0; j < 4; ++j)
            v[j] = binimg ? xpix[(size_t)(icch * 32 + kt * 4 + j) << 10] : 0.f;
    };
    auto buildX4_st = [&](int icch, int kt, uint32_t xoff, const float* v) {
        if (!bact) return;
        union { __half2 h2[2]; uint2 u2; } P;
        const int styb = icch * 32 + kt * 4;
        P.h2[0] = __halves2half2(__float2half(v[0] * s_sty[styb + 0]),
                                 __float2half(v[1] * s_sty[styb + 1]));
        P.h2[1] = __halves2half2(__float2half(v[2] * s_sty[styb + 2]),
                                 __float2half(v[3] * s_sty[styb + 3]));
        *(uint2*)(smem + xoff + (uint32_t)tid * RS + kt * 8) = P.u2;
    };
    auto ldsmSub = [&](int fb, uint32_t wimg, uint32_t xoff, uint32_t toff,
                       uint32_t kb) {
#pragma unroll
        for (int m = 0; m < 4; ++m)
            LDMX4(ah[fb][m],
                  sb + wimg + (uint32_t)(wm * 64 + m * 16) * RS + kb + aoff);
#pragma unroll
        for (int n = 0; n < 4; ++n)
            LDMX2(bh[fb][n], sb + xoff + toff + bb[n] + kb);
    };
    auto mmaSub = [&](int fb) {
#pragma unroll
        for (int m = 0; m < 4; ++m)
#pragma unroll
            for (int n = 0; n < 4; ++n) MMA16816(acc[m][n], ah[fb][m], bh[fb][n]);
    };

    // ---- prologue: build X chunk 0, load W macro 0 (taps 0-2) ----
    {
#pragma unroll
        for (int kt = 0; kt < 8; ++kt) {
            float v[4];
            buildX4_ld(0, kt, v);
            buildX4_st(0, kt, XOFF(0), v);
        }
        issueW3(0, WOFF(0));
        CP_WAIT0();
        __syncthreads();
    }

    // ---- main loop: 16 ic-chunks x 3 macro-stages (3 taps each) ----
#pragma unroll 1
    for (int icch = 0; icch < 16; ++icch) {
        const uint32_t xoff = XOFF(icch & 1);
        const uint32_t xnext = XOFF((icch & 1) ^ 1);
        const bool morex = (icch + 1 < 16);
#pragma unroll 1
        for (int tg = 0; tg < 3; ++tg) {
            const int mc = icch * 3 + tg;          // macro-chunk index
            const uint32_t woff = WOFF(mc & 1);
            if (mc + 1 < 48) issueW3(mc + 1, WOFF((mc & 1) ^ 1));
            // taps this stage: tg*3 + i, i=0..2 -> kh = tg-1, kw = i-1
            const uint32_t trow = (uint32_t)((tg - 1) * 34 * (int)RS);

            // pipelined 6 subtiles: s -> (tap i = s>>1, kb = (s&1)*32)
            ldsmSub(0, woff + 0 * WIMG, xoff, trow + (0 - 1) * (int)RS, 0u);
#pragma unroll
            for (int s = 0; s < 6; ++s) {
                const int i = s >> 1;
                const int fb = s & 1;
                if (s < 5) {
                    const int i2 = (s + 1) >> 1;
                    ldsmSub(fb ^ 1, woff + (uint32_t)i2 * WIMG, xoff,
                            trow + (uint32_t)((i2 - 1) * (int)RS),
                            (uint32_t)(((s + 1) & 1) * 32));
                }
                const int tap = tg * 3 + i;
                const bool bld = morex && tap < 8;
                if ((s & 1) == 0) {            // even: LDG early
                    float v[4];
                    if (bld) buildX4_ld(icch + 1, tap, v);
                    mmaSub(fb);
                    if (bld) buildX4_st(icch + 1, tap, xnext, v);
                } else {
                    mmaSub(fb);
                }
            }
            if (mc + 1 < 48) CP_WAIT0();
            __syncthreads();
        }
    }

    // ---- epilogue: demodulate + store ----
    float* ob = out + (size_t)b * NC * HW2 + (size_t)octile * 128 * HW2 +
                pixtile * 128;
#pragma unroll
    for (int m = 0; m < 4; ++m) {
        const int r0 = wm * 64 + m * 16 + (lane >> 2);
        const float sg0 = s_sig[r0], sg1 = s_sig[r0 + 8];
#pragma unroll
        for (int n = 0; n < 4; ++n) {
            const int col = wn * 32 + n * 8 + (lane & 3) * 2;
            float2 v0 = make_float2(acc[m][n][0] * sg0, acc[m][n][1] * sg0);
            float2 v1 = make_float2(acc[m][n][2] * sg1, acc[m][n][3] * sg1);
            *(float2*)(ob + (size_t)r0 * HW2 + col) = v0;
            *(float2*)(ob + (size_t)(r0 + 8) * HW2 + col) = v1;
        }
    }
}

// ---------------------------------------------------------------------------
extern "C" void kernel_launch(void* const* d_in, const int* in_sizes, int n_in,
                              void* d_out, int out_size) {
    const float* x      = (const float*)d_in[0];
    const float* style  = (const float*)d_in[1];
    const float* weight = (const float*)d_in[2];
    float* out          = (float*)d_out;
    (void)in_sizes; (void)n_in; (void)out_size;

    const float gain = 1.0f / sqrtf(4608.0f);

    cudaFuncSetAttribute(conv_mma, cudaFuncAttributeMaxDynamicSharedMemorySize,
                         SM_TOTAL);

    prep_all<<<dim3(16, 4), 256>>>(weight, gain);
    sigma_kernel<<<dim3(64, 16), 256>>>(style);
    conv_mma<<<dim3(8, 4, 16), 256, SM_TOTAL>>>(x, style, out);
}

// round 15
// speedup vs baseline: 1.2238x; 1.2238x over previous
#include <cuda_runtime.h>
#include <cuda_fp16.h>
#include <cstdint>
#include <math.h>

// ModulatedConv2D via mma.sync (pure fp16 operands, fp32 accum) implicit GEMM.
// y = sigma[b,o] * conv2d_same(x * style[b,i], GAIN*weight)
// x[16,512,32,32], style[16,512], weight[512,512,3,3] -> out[16,512,32,32]
// R15 = R12 base + warp-parity subtile ordering (de-phase LSU/tensor bursts)
//       + B fragments via ldmatrix.x4 (8 -> 6 LDSM per warp-subtile).

#define NB 16
#define NC 512
#define HW2 1024
#define EPSV 1e-8f
#define NCHUNK 144   // 16 ic-chunks * 9 taps, K=32 each

static __device__ float g_wsq[NC * NC];
static __device__ float g_sigma[NB * NC];
// weight tiles fp16: [octile(4)][chunk(144)] -> [128 oc][32 k] (8KB)
static __device__ unsigned char g_btiles[(size_t)4 * NCHUNK * 8192];

// ---------------------------------------------------------------------------
__device__ __forceinline__ uint32_t smem_u32(const void* p) {
    uint32_t a;
    asm("{ .reg .u64 t; cvta.to.shared.u64 t, %1; cvt.u32.u64 %0, t; }"
        : "=r"(a) : "l"(p));
    return a;
}
#define CP_ASYNC16(dst, src) \
    asm volatile("cp.async.cg.shared.global [%0], [%1], 16;" :: "r"(dst), "l"(src))
#define CP_COMMIT() asm volatile("cp.async.commit_group;")
#define CP_WAIT0()  asm volatile("cp.async.wait_group 0;" ::: "memory")

#define LDMX4(r, addr) \
    asm volatile("ldmatrix.sync.aligned.m8n8.x4.shared.b16 {%0,%1,%2,%3}, [%4];" \
                 : "=r"((r)[0]), "=r"((r)[1]), "=r"((r)[2]), "=r"((r)[3]) : "r"(addr))

#define MMA16816(d, a, b) \
    asm volatile("mma.sync.aligned.m16n8k16.row.col.f32.f16.f16.f32 " \
                 "{%0,%1,%2,%3}, {%4,%5,%6,%7}, {%8,%9}, {%0,%1,%2,%3};" \
                 : "+f"((d)[0]), "+f"((d)[1]), "+f"((d)[2]), "+f"((d)[3]) \
                 : "r"((a)[0]), "r"((a)[1]), "r"((a)[2]), "r"((a)[3]), \
                   "r"((b)[0]), "r"((b)[1]))

// ---------------------------------------------------------------------------
// wsq[oc,ic] = sum_k (GAIN*w)^2
// ---------------------------------------------------------------------------
__global__ void wsq_kernel(const float* __restrict__ weight, float gain) {
    const int oc0 = blockIdx.x * 64;
    const int ic0 = blockIdx.y * 8;
    __shared__ float sw[64][73];
    for (int idx = threadIdx.x; idx < 64 * 72; idx += 256) {
        int o = idx / 72, ik = idx % 72;
        sw[o][ik] = weight[(size_t)(oc0 + o) * 4608 + ic0 * 9 + ik] * gain;
    }
    __syncthreads();
    for (int idx = threadIdx.x; idx < 64 * 8; idx += 256) {
        int o = idx >> 3, i = idx & 7;
        float s = 0.f;
#pragma unroll
        for (int k = 0; k < 9; ++k) { float v = sw[o][i * 9 + k]; s += v * v; }
        g_wsq[(oc0 + o) * NC + ic0 + i] = s;
    }
}

__global__ void sigma_kernel(const float* __restrict__ style) {
    const int b = blockIdx.y;
    const int warp = threadIdx.x >> 5, lane = threadIdx.x & 31;
    const int oc = blockIdx.x * 8 + warp;
    float v = 0.f;
    for (int i = lane; i < NC; i += 32) {
        float s = style[b * NC + i];
        v += s * s * g_wsq[oc * NC + i];
    }
#pragma unroll
    for (int off = 16; off; off >>= 1) v += __shfl_xor_sync(0xffffffffu, v, off);
    if (lane == 0) g_sigma[b * NC + oc] = rsqrtf(v + EPSV);
}

// ---------------------------------------------------------------------------
// prep: weights -> fp16 tiles, layout [oc(128)][k(32)] packed 64B rows.
// grid (144, 4), 256 threads: thread = (oc 0..127) x (khalf 0..1)
// ---------------------------------------------------------------------------
__global__ void prep_b(const float* __restrict__ weight, float gain) {
    const int cc = blockIdx.x, octile = blockIdx.y;
    const int icch = cc / 9, tap = cc % 9;
    const int ocl = threadIdx.x >> 1;
    const int kh = (threadIdx.x & 1) * 16;
    const int oc = octile * 128 + ocl;
    const float* wr = weight + (size_t)oc * 4608 + (size_t)(icch * 32 + kh) * 9 + tap;
    union { __half2 h2[8]; uint4 u4[2]; } H;
#pragma unroll
    for (int j = 0; j < 8; ++j) {
        float v0 = wr[(2 * j) * 9] * gain;
        float v1 = wr[(2 * j + 1) * 9] * gain;
        H.h2[j] = __halves2half2(__float2half(v0), __float2half(v1));
    }
    unsigned char* blk = g_btiles + (size_t)(octile * NCHUNK + cc) * 8192;
    uint4* dh = (uint4*)(blk + ocl * 64 + kh * 2);
    dh[0] = H.u4[0]; dh[1] = H.u4[1];
}

// ---------------------------------------------------------------------------
// conv: grid (8 pixtiles, 4 octiles, 16 b), 256 threads (8 warps).
// CTA tile: M=128 oc x N=128 pix, K-chunk 32 (one tap), 144 chunks.
// X stored per ic-chunk as halo tile: 204 "pixel rows" (6 img rows x 34 cols,
// zero-padded) x 32 k halves, 80B row stride. Tap = address offset.
// smem: W0@0 W1@10240 | X0@20480 X1@36800 (16320 each) | sig@53120 sty@53632
// ---------------------------------------------------------------------------
#define RS 80u          // row stride bytes (40 halves)
#define WOFF(buf) ((uint32_t)(buf) * 10240u)
#define XOFF(buf) (20480u + (uint32_t)(buf) * 16320u)
#define SM_TOTAL 55680

__global__ void __launch_bounds__(256, 2)
conv_mma(const float* __restrict__ x, const float* __restrict__ style,
         float* __restrict__ out) {
    extern __shared__ char smem[];
    const uint32_t sb = smem_u32(smem);
    const int tid = threadIdx.x;
    const int lane = tid & 31, wid = tid >> 5;
    const int wm = wid & 1;        // m warp (oc): 0..1 -> offset wm*64
    const int wn = wid >> 1;       // n warp (pix row): 0..3
    const int pixtile = blockIdx.x, octile = blockIdx.y, b = blockIdx.z;

    float* s_sig = (float*)(smem + 53120);
    float* s_sty = (float*)(smem + 53632);
    for (int i = tid; i < 128; i += 256) s_sig[i] = g_sigma[b * NC + octile * 128 + i];
    for (int i = tid; i < NC; i += 256) s_sty[i] = style[b * NC + i];
    __syncthreads();

    const float* xb = x + (size_t)b * NC * HW2;
    const unsigned char* wbase = g_btiles + (size_t)octile * NCHUNK * 8192;

    // ---- X-build coords: thread t handles halo-tile pixel row t (0..203) ----
    const bool bact = tid < 204;
    const int blr = tid / 34;                 // local halo row 0..5
    const int bcc = tid % 34 - 1;             // image col -1..32
    const int bimgrow = pixtile * 4 - 1 + blr;
    const bool binimg = bact && ((unsigned)bimgrow < 32u) && ((unsigned)bcc < 32u);
    const float* xpix = xb + (binimg ? (bimgrow * 32 + bcc) : 0);

    // ldmatrix per-lane offsets
    const uint32_t aoff = (uint32_t)(lane & 15) * RS + (uint32_t)(lane >> 4) * 16u;
    // B x4 lane base (kh=kw=0) for n-pair j (n = 2j + (lane>>4)):
    //   halo row = (wn+1)*34 + n*8 + (lane&7) + 1 ; k-half = (lane>>3)&1
    uint32_t bb4[2];
#pragma unroll
    for (int j = 0; j < 2; ++j)
        bb4[j] = (uint32_t)(((wn + 1) * 34 + (2 * j + (lane >> 4)) * 8 +
                             (lane & 7) + 1)) * RS +
                 (uint32_t)((lane >> 3) & 1) * 16u;

    float acc[4][4][4];
#pragma unroll
    for (int m = 0; m < 4; ++m)
#pragma unroll
        for (int n = 0; n < 4; ++n)
#pragma unroll
            for (int r = 0; r < 4; ++r) acc[m][n][r] = 0.f;

    // ---- helpers ----
    auto issueW = [&](int c, uint32_t woff) {
        const unsigned char* src = wbase + (size_t)c * 8192;
#pragma unroll
        for (int j = 0; j < 2; ++j) {
            int cidx = tid + j * 256;               // 0..511 16B chunks
            int row = cidx >> 2, off = cidx & 3;
            CP_ASYNC16(sb + woff + row * RS + off * 16, src + cidx * 16);
        }
        CP_COMMIT();
    };
    // build 4 k-slices (kt*4 .. kt*4+3) of ic-chunk icch into X buffer xoff
    auto buildX4_ld = [&](int icch, int kt, float* v) {
#pragma unroll
        for (int j = 0; j < 4; ++j)
            v[j] = binimg ? xpix[(size_t)(icch * 32 + kt * 4 + j) << 10] : 0.f;
    };
    auto buildX4_st = [&](int icch, int kt, uint32_t xoff, const float* v) {
        if (!bact) return;
        union { __half2 h2[2]; uint2 u2; } P;
        const int styb = icch * 32 + kt * 4;
        P.h2[0] = __halves2half2(__float2half(v[0] * s_sty[styb + 0]),
                                 __float2half(v[1] * s_sty[styb + 1]));
        P.h2[1] = __halves2half2(__float2half(v[2] * s_sty[styb + 2]),
                                 __float2half(v[3] * s_sty[styb + 3]));
        *(uint2*)(smem + xoff + (uint32_t)tid * RS + kt * 8) = P.u2;
    };
    // one K=16 subtile of MMAs: W buffer woff, X buffer xoff, tap offset toff
    auto mmaKS = [&](uint32_t woff, uint32_t xoff, uint32_t toff, uint32_t kb) {
        uint32_t ah[4][4], bh[2][4];
#pragma unroll
        for (int m = 0; m < 4; ++m)
            LDMX4(ah[m], sb + woff + (uint32_t)(wm * 64 + m * 16) * RS + kb + aoff);
#pragma unroll
        for (int j = 0; j < 2; ++j)
            LDMX4(bh[j], sb + xoff + toff + bb4[j] + kb);
#pragma unroll
        for (int m = 0; m < 4; ++m)
#pragma unroll
            for (int n = 0; n < 4; ++n)
                MMA16816(acc[m][n], ah[m], (&bh[n >> 1][(n & 1) * 2]));
    };

    // ---- prologue: build X chunk 0, load W chunk 0 ----
    {
#pragma unroll
        for (int kt = 0; kt < 8; ++kt) {
            float v[4];
            buildX4_ld(0, kt, v);
            buildX4_st(0, kt, XOFF(0), v);
        }
        issueW(0, WOFF(0));
        CP_WAIT0();
        __syncthreads();
    }

    // subtile order alternates by warp parity to de-phase LSU/tensor bursts
    const uint32_t kb_first = (wid & 1) ? 32u : 0u;
    const uint32_t kb_second = kb_first ^ 32u;

    // ---- main loop over 16 ic-chunks x 9 taps ----
#pragma unroll 1
    for (int icch = 0; icch < 16; ++icch) {
        const uint32_t xoff = XOFF(icch & 1);
        const uint32_t xnext = XOFF((icch & 1) ^ 1);
        const bool morex = (icch + 1 < 16);
#pragma unroll 1
        for (int tap = 0; tap < 9; ++tap) {
            const int c = icch * 9 + tap;
            const uint32_t woff = WOFF(c & 1);
            const bool morec = (c + 1 < NCHUNK);
            if (morec) issueW(c + 1, WOFF((c & 1) ^ 1));
            const int kh = tap / 3 - 1, kw = tap % 3 - 1;
            const uint32_t toff = (uint32_t)((kh * 34 + kw) * (int)RS);
            float v[4];
            const bool bld = morex && tap < 8;
            if (bld) buildX4_ld(icch + 1, tap, v);     // LDG early (hidden)
            mmaKS(woff, xoff, toff, kb_first);         // K subtile A
            if (bld) buildX4_st(icch + 1, tap, xnext, v);
            mmaKS(woff, xoff, toff, kb_second);        // K subtile B
            if (morec) CP_WAIT0();
            __syncthreads();
        }
    }

    // ---- epilogue: demodulate + store ----
    float* ob = out + (size_t)b * NC * HW2 + (size_t)octile * 128 * HW2 +
                pixtile * 128;
#pragma unroll
    for (int m = 0; m < 4; ++m) {
        const int r0 = wm * 64 + m * 16 + (lane >> 2);
        const float sg0 = s_sig[r0], sg1 = s_sig[r0 + 8];
#pragma unroll
        for (int n = 0; n < 4; ++n) {
            const int col = wn * 32 + n * 8 + (lane & 3) * 2;
            float2 v0 = make_float2(acc[m][n][0] * sg0, acc[m][n][1] * sg0);
            float2 v1 = make_float2(acc[m][n][2] * sg1, acc[m][n][3] * sg1);
            *(float2*)(ob + (size_t)r0 * HW2 + col) = v0;
            *(float2*)(ob + (size_t)(r0 + 8) * HW2 + col) = v1;
        }
    }
}

// ---------------------------------------------------------------------------
extern "C" void kernel_launch(void* const* d_in, const int* in_sizes, int n_in,
                              void* d_out, int out_size) {
    const float* x      = (const float*)d_in[0];
    const float* style  = (const float*)d_in[1];
    const float* weight = (const float*)d_in[2];
    float* out          = (float*)d_out;
    (void)in_sizes; (void)n_in; (void)out_size;

    const float gain = 1.0f / sqrtf(4608.0f);

    cudaFuncSetAttribute(conv_mma, cudaFuncAttributeMaxDynamicSharedMemorySize,
                         SM_TOTAL);

    wsq_kernel<<<dim3(8, 64), 256>>>(weight, gain);
    prep_b<<<dim3(NCHUNK, 4), 256>>>(weight, gain);
    sigma_kernel<<<dim3(64, 16), 256>>>(style);
    conv_mma<<<dim3(8, 4, 16), 256, SM_TOTAL>>>(x, style, out);
}